// round 1
// baseline (speedup 1.0000x reference)
#include <cuda_runtime.h>
#include <math.h>

// Problem constants
#define BB 2
#define TT 2048
#define CC 2048
#define HH 16
#define HD 128
#define MLPD 8192
#define BT (BB*TT)          // 4096 rows
#define EPS 1e-5f

// ---------------------------------------------------------------------------
// Scratch (device globals; no allocations allowed)
// ---------------------------------------------------------------------------
__device__ float g_h[(size_t)BT*CC];     // rmsnorm output
__device__ float g_q[(size_t)BT*CC];
__device__ float g_k[(size_t)BT*CC];
__device__ float g_v[(size_t)BT*CC];
__device__ float g_att[(size_t)BT*CC];   // attention output (pre-proj)
__device__ float g_x1[(size_t)BT*CC];    // x after attention residual
__device__ float g_m[(size_t)BT*MLPD];   // MLP hidden

// ---------------------------------------------------------------------------
// RMSNorm: one block per row
// ---------------------------------------------------------------------------
__global__ void rmsnorm_kernel(const float* __restrict__ x, float* __restrict__ o) {
    int row = blockIdx.x;
    const float* xr = x + (size_t)row * CC;
    float ss = 0.f;
    for (int c = threadIdx.x; c < CC; c += blockDim.x) {
        float vv = xr[c];
        ss += vv * vv;
    }
    __shared__ float red[32];
    #pragma unroll
    for (int off = 16; off; off >>= 1) ss += __shfl_xor_sync(0xffffffffu, ss, off);
    int wid = threadIdx.x >> 5, lane = threadIdx.x & 31;
    if (lane == 0) red[wid] = ss;
    __syncthreads();
    if (wid == 0) {
        float v2 = lane < (blockDim.x >> 5) ? red[lane] : 0.f;
        #pragma unroll
        for (int off = 16; off; off >>= 1) v2 += __shfl_xor_sync(0xffffffffu, v2, off);
        if (lane == 0) red[0] = rsqrtf(v2 / (float)CC + EPS);
    }
    __syncthreads();
    float r = red[0];
    float* orow = o + (size_t)row * CC;
    for (int c = threadIdx.x; c < CC; c += blockDim.x) orow[c] = xr[c] * r;
}

// ---------------------------------------------------------------------------
// GEMM: C[M,N] = A[M,K] @ W[N,K]^T   (both operands K-contiguous)
// epilogue: 0 = none, 1 = +Res, 2 = relu^2
// 128x128 tile, 256 threads, 8x8 per thread
// ---------------------------------------------------------------------------
enum { EPI_NONE = 0, EPI_ADD = 1, EPI_RELU2 = 2 };

template <int EPI>
__global__ __launch_bounds__(256) void gemm_tn(
    const float* __restrict__ A, const float* __restrict__ W,
    const float* __restrict__ Res, float* __restrict__ C,
    int M, int N, int K)
{
    __shared__ float As[16][128];
    __shared__ float Bs[16][128];
    int tid = threadIdx.x;
    int bm = blockIdx.y * 128;
    int bn = blockIdx.x * 128;
    int tx = tid & 15, ty = tid >> 4;

    float acc[8][8];
    #pragma unroll
    for (int i = 0; i < 8; i++)
        #pragma unroll
        for (int j = 0; j < 8; j++) acc[i][j] = 0.f;

    for (int k0 = 0; k0 < K; k0 += 16) {
        #pragma unroll
        for (int i = 0; i < 2; i++) {
            int lin = tid + i * 256;     // 0..511
            int r = lin >> 2;            // 0..127
            int c4 = (lin & 3) * 4;      // 0,4,8,12
            float4 va = *reinterpret_cast<const float4*>(&A[(size_t)(bm + r) * K + k0 + c4]);
            As[c4 + 0][r] = va.x; As[c4 + 1][r] = va.y;
            As[c4 + 2][r] = va.z; As[c4 + 3][r] = va.w;
            float4 vb = *reinterpret_cast<const float4*>(&W[(size_t)(bn + r) * K + k0 + c4]);
            Bs[c4 + 0][r] = vb.x; Bs[c4 + 1][r] = vb.y;
            Bs[c4 + 2][r] = vb.z; Bs[c4 + 3][r] = vb.w;
        }
        __syncthreads();
        #pragma unroll
        for (int kk = 0; kk < 16; kk++) {
            float a[8], b[8];
            #pragma unroll
            for (int i = 0; i < 4; i++) {
                a[i]     = As[kk][ty * 4 + i];
                a[4 + i] = As[kk][64 + ty * 4 + i];
                b[i]     = Bs[kk][tx * 4 + i];
                b[4 + i] = Bs[kk][64 + tx * 4 + i];
            }
            #pragma unroll
            for (int i = 0; i < 8; i++)
                #pragma unroll
                for (int j = 0; j < 8; j++)
                    acc[i][j] = fmaf(a[i], b[j], acc[i][j]);
        }
        __syncthreads();
    }

    #pragma unroll
    for (int i = 0; i < 8; i++) {
        int r = bm + ((i < 4) ? (ty * 4 + i) : (64 + ty * 4 + (i - 4)));
        #pragma unroll
        for (int j = 0; j < 8; j++) {
            int c = bn + ((j < 4) ? (tx * 4 + j) : (64 + tx * 4 + (j - 4)));
            float v = acc[i][j];
            if (EPI == EPI_RELU2) { v = fmaxf(v, 0.f); v = v * v; }
            else if (EPI == EPI_ADD) { v += Res[(size_t)r * N + c]; }
            C[(size_t)r * N + c] = v;
        }
    }
}

// ---------------------------------------------------------------------------
// Flash-style causal attention. Q/K/V layout: [B, T, H*HD] (H,HD packed in C)
// Block = (qtile, head, batch). BM=64, BN=64, HD=128, 256 threads.
// ---------------------------------------------------------------------------
struct AttSmem {
    float Q[64][128];
    float K[64][128];
    float V[64][128];
    float S[64][65];
    float mrow[64];
    float lrow[64];
    float arow[64];
};

extern __shared__ float att_raw[];

__global__ __launch_bounds__(256) void attn_kernel(
    const float* __restrict__ q, const float* __restrict__ k,
    const float* __restrict__ v, float* __restrict__ o)
{
    AttSmem* sm = reinterpret_cast<AttSmem*>(att_raw);
    int tid = threadIdx.x;
    int qt = blockIdx.x, h = blockIdx.y, b = blockIdx.z;
    int qbase = qt * 64;
    const float scale = 0.08838834764831845f;  // 1/sqrt(128)
    size_t base = ((size_t)b * TT) * CC + (size_t)h * HD;

    // Load Q (scaled)
    #pragma unroll
    for (int i = 0; i < 8; i++) {
        int lin = tid + i * 256;       // float4 index 0..2047
        int r = lin >> 5;              // 0..63
        int c4 = (lin & 31) * 4;       // 0..124
        float4 vq = *reinterpret_cast<const float4*>(&q[base + (size_t)(qbase + r) * CC + c4]);
        vq.x *= scale; vq.y *= scale; vq.z *= scale; vq.w *= scale;
        *reinterpret_cast<float4*>(&sm->Q[r][c4]) = vq;
    }
    if (tid < 64) { sm->mrow[tid] = -1e30f; sm->lrow[tid] = 0.f; }

    float acc[4][8];
    #pragma unroll
    for (int i = 0; i < 4; i++)
        #pragma unroll
        for (int j = 0; j < 8; j++) acc[i][j] = 0.f;

    int mt = tid >> 4;   // 0..15 -> rows mt*4..mt*4+3
    int dt = tid & 15;   // 0..15 -> cols dt*8..dt*8+7
    __syncthreads();

    for (int nt = 0; nt <= qt; nt++) {
        int kbase = nt * 64;
        // Load K and V tiles
        #pragma unroll
        for (int i = 0; i < 8; i++) {
            int lin = tid + i * 256;
            int r = lin >> 5;
            int c4 = (lin & 31) * 4;
            *reinterpret_cast<float4*>(&sm->K[r][c4]) =
                *reinterpret_cast<const float4*>(&k[base + (size_t)(kbase + r) * CC + c4]);
            *reinterpret_cast<float4*>(&sm->V[r][c4]) =
                *reinterpret_cast<const float4*>(&v[base + (size_t)(kbase + r) * CC + c4]);
        }
        __syncthreads();

        // S = Q K^T  (each thread: 4x4)
        {
            int r0 = (tid >> 4) * 4, c0 = (tid & 15) * 4;
            float s[4][4];
            #pragma unroll
            for (int i = 0; i < 4; i++)
                #pragma unroll
                for (int j = 0; j < 4; j++) s[i][j] = 0.f;
            for (int d = 0; d < 128; d++) {
                float a0 = sm->Q[r0 + 0][d], a1 = sm->Q[r0 + 1][d];
                float a2 = sm->Q[r0 + 2][d], a3 = sm->Q[r0 + 3][d];
                float b0 = sm->K[c0 + 0][d], b1 = sm->K[c0 + 1][d];
                float b2 = sm->K[c0 + 2][d], b3 = sm->K[c0 + 3][d];
                s[0][0] = fmaf(a0, b0, s[0][0]); s[0][1] = fmaf(a0, b1, s[0][1]);
                s[0][2] = fmaf(a0, b2, s[0][2]); s[0][3] = fmaf(a0, b3, s[0][3]);
                s[1][0] = fmaf(a1, b0, s[1][0]); s[1][1] = fmaf(a1, b1, s[1][1]);
                s[1][2] = fmaf(a1, b2, s[1][2]); s[1][3] = fmaf(a1, b3, s[1][3]);
                s[2][0] = fmaf(a2, b0, s[2][0]); s[2][1] = fmaf(a2, b1, s[2][1]);
                s[2][2] = fmaf(a2, b2, s[2][2]); s[2][3] = fmaf(a2, b3, s[2][3]);
                s[3][0] = fmaf(a3, b0, s[3][0]); s[3][1] = fmaf(a3, b1, s[3][1]);
                s[3][2] = fmaf(a3, b2, s[3][2]); s[3][3] = fmaf(a3, b3, s[3][3]);
            }
            #pragma unroll
            for (int i = 0; i < 4; i++)
                #pragma unroll
                for (int j = 0; j < 4; j++) {
                    int kg = kbase + c0 + j, qg = qbase + r0 + i;
                    sm->S[r0 + i][c0 + j] = (kg <= qg) ? s[i][j] : -1e30f;
                }
        }
        __syncthreads();

        // Online softmax update (4 threads per row)
        {
            int row = tid >> 2, sub = tid & 3;
            float tmax = -1e30f;
            #pragma unroll
            for (int c = 0; c < 16; c++) tmax = fmaxf(tmax, sm->S[row][sub * 16 + c]);
            tmax = fmaxf(tmax, __shfl_xor_sync(0xffffffffu, tmax, 1));
            tmax = fmaxf(tmax, __shfl_xor_sync(0xffffffffu, tmax, 2));
            float mprev = sm->mrow[row];
            float newm = fmaxf(mprev, tmax);
            float ls = 0.f;
            #pragma unroll
            for (int c = 0; c < 16; c++) {
                float p = __expf(sm->S[row][sub * 16 + c] - newm);
                sm->S[row][sub * 16 + c] = p;
                ls += p;
            }
            ls += __shfl_xor_sync(0xffffffffu, ls, 1);
            ls += __shfl_xor_sync(0xffffffffu, ls, 2);
            if (sub == 0) {
                float al = __expf(mprev - newm);
                sm->mrow[row] = newm;
                sm->lrow[row] = sm->lrow[row] * al + ls;
                sm->arow[row] = al;
            }
        }
        __syncthreads();

        // Rescale and accumulate O += P V
        #pragma unroll
        for (int i = 0; i < 4; i++) {
            float al = sm->arow[mt * 4 + i];
            #pragma unroll
            for (int j = 0; j < 8; j++) acc[i][j] *= al;
        }
        for (int kk = 0; kk < 64; kk++) {
            float4 v0 = *reinterpret_cast<const float4*>(&sm->V[kk][dt * 8]);
            float4 v1 = *reinterpret_cast<const float4*>(&sm->V[kk][dt * 8 + 4]);
            float vv[8] = {v0.x, v0.y, v0.z, v0.w, v1.x, v1.y, v1.z, v1.w};
            #pragma unroll
            for (int i = 0; i < 4; i++) {
                float p = sm->S[mt * 4 + i][kk];
                #pragma unroll
                for (int j = 0; j < 8; j++) acc[i][j] = fmaf(p, vv[j], acc[i][j]);
            }
        }
        __syncthreads();
    }

    // Write O = acc / l
    #pragma unroll
    for (int i = 0; i < 4; i++) {
        int rm = mt * 4 + i;
        float inv = 1.f / sm->lrow[rm];
        float4 o0, o1;
        o0.x = acc[i][0] * inv; o0.y = acc[i][1] * inv;
        o0.z = acc[i][2] * inv; o0.w = acc[i][3] * inv;
        o1.x = acc[i][4] * inv; o1.y = acc[i][5] * inv;
        o1.z = acc[i][6] * inv; o1.w = acc[i][7] * inv;
        size_t obase = base + (size_t)(qbase + rm) * CC + dt * 8;
        *reinterpret_cast<float4*>(&o[obase]) = o0;
        *reinterpret_cast<float4*>(&o[obase + 4]) = o1;
    }
}

// ---------------------------------------------------------------------------
// Launch
// ---------------------------------------------------------------------------
extern "C" void kernel_launch(void* const* d_in, const int* in_sizes, int n_in,
                              void* d_out, int out_size) {
    const float* x   = (const float*)d_in[0];
    const float* wq  = (const float*)d_in[1];
    const float* wk  = (const float*)d_in[2];
    const float* wv  = (const float*)d_in[3];
    const float* wo  = (const float*)d_in[4];
    const float* fc1 = (const float*)d_in[5];
    const float* fc2 = (const float*)d_in[6];
    float* out = (float*)d_out;

    float *h, *q, *k, *v, *att, *x1, *m;
    cudaGetSymbolAddress((void**)&h,   g_h);
    cudaGetSymbolAddress((void**)&q,   g_q);
    cudaGetSymbolAddress((void**)&k,   g_k);
    cudaGetSymbolAddress((void**)&v,   g_v);
    cudaGetSymbolAddress((void**)&att, g_att);
    cudaGetSymbolAddress((void**)&x1,  g_x1);
    cudaGetSymbolAddress((void**)&m,   g_m);

    // Attention needs >48KB dynamic smem
    static_assert(sizeof(AttSmem) <= 120 * 1024, "smem");
    cudaFuncSetAttribute(attn_kernel, cudaFuncAttributeMaxDynamicSharedMemorySize,
                         (int)sizeof(AttSmem));

    dim3 thr(256);

    // 1) h = rmsnorm(x)
    rmsnorm_kernel<<<BT, thr>>>(x, h);

    // 2-4) q,k,v = h @ w{q,k,v}^T
    dim3 g_qkv(CC / 128, BT / 128);
    gemm_tn<EPI_NONE><<<g_qkv, thr>>>(h, wq, nullptr, q, BT, CC, CC);
    gemm_tn<EPI_NONE><<<g_qkv, thr>>>(h, wk, nullptr, k, BT, CC, CC);
    gemm_tn<EPI_NONE><<<g_qkv, thr>>>(h, wv, nullptr, v, BT, CC, CC);

    // 5) causal attention
    dim3 g_att_grid(TT / 64, HH, BB);
    attn_kernel<<<g_att_grid, thr, sizeof(AttSmem)>>>(q, k, v, att);

    // 6) x1 = x + att @ wo^T
    gemm_tn<EPI_ADD><<<g_qkv, thr>>>(att, wo, x, x1, BT, CC, CC);

    // 7) h = rmsnorm(x1)
    rmsnorm_kernel<<<BT, thr>>>(x1, h);

    // 8) m = relu(h @ fc1^T)^2
    dim3 g_fc1(MLPD / 128, BT / 128);
    gemm_tn<EPI_RELU2><<<g_fc1, thr>>>(h, fc1, nullptr, m, BT, MLPD, CC);

    // 9) out = x1 + m @ fc2^T
    dim3 g_fc2(CC / 128, BT / 128);
    gemm_tn<EPI_ADD><<<g_fc2, thr>>>(m, fc2, x1, out, BT, CC, MLPD);
}

// round 5
// speedup vs baseline: 1.6034x; 1.6034x over previous
#include <cuda_runtime.h>
#include <cuda_bf16.h>
#include <cstdint>
#include <stdint.h>
#include <math.h>

// Problem constants
#define BB 2
#define TT 2048
#define CC 2048
#define HH 16
#define HD 128
#define MLPD 8192
#define BT (BB*TT)          // 4096 rows
#define EPS 1e-5f

// ---------------------------------------------------------------------------
// Scratch (device globals; no allocations allowed)
// ---------------------------------------------------------------------------
__device__ float g_h[(size_t)BT*CC];     // rmsnorm output
__device__ float g_q[(size_t)BT*CC];
__device__ float g_k[(size_t)BT*CC];
__device__ float g_v[(size_t)BT*CC];
__device__ float g_att[(size_t)BT*CC];   // attention output (pre-proj)
__device__ float g_x1[(size_t)BT*CC];    // x after attention residual
__device__ float g_m[(size_t)BT*MLPD];   // MLP hidden

// ---------------------------------------------------------------------------
// RMSNorm: one block per row
// ---------------------------------------------------------------------------
__global__ void rmsnorm_kernel(const float* __restrict__ x, float* __restrict__ o) {
    int row = blockIdx.x;
    const float* xr = x + (size_t)row * CC;
    float ss = 0.f;
    for (int c = threadIdx.x; c < CC; c += blockDim.x) {
        float vv = xr[c];
        ss += vv * vv;
    }
    __shared__ float red[32];
    #pragma unroll
    for (int off = 16; off; off >>= 1) ss += __shfl_xor_sync(0xffffffffu, ss, off);
    int wid = threadIdx.x >> 5, lane = threadIdx.x & 31;
    if (lane == 0) red[wid] = ss;
    __syncthreads();
    if (wid == 0) {
        float v2 = lane < (blockDim.x >> 5) ? red[lane] : 0.f;
        #pragma unroll
        for (int off = 16; off; off >>= 1) v2 += __shfl_xor_sync(0xffffffffu, v2, off);
        if (lane == 0) red[0] = rsqrtf(v2 / (float)CC + EPS);
    }
    __syncthreads();
    float r = red[0];
    float* orow = o + (size_t)row * CC;
    for (int c = threadIdx.x; c < CC; c += blockDim.x) orow[c] = xr[c] * r;
}

// ---------------------------------------------------------------------------
// bf16x3 split-precision GEMM via mma.sync.m16n8k16
// C[M,N] = A[M,K] @ W[N,K]^T  (both K-contiguous)
// a = a_hi + a_lo (bf16 each); acc += ahi*bhi + ahi*blo + alo*bhi (fp32 acc)
// Block tile 128x128x32, 512 threads, warp grid 4x4 of 32x32 warp tiles.
// ---------------------------------------------------------------------------
enum { EPI_NONE = 0, EPI_ADD = 1, EPI_RELU2 = 2 };

#define PITCH 40            // bf16 elems per smem row (32 + 8 pad); 20 words
#define TILE3 (128*PITCH)   // bf16 elems per tile part
#define SMEM3 (2*4*TILE3*2) // bytes: 2 stages x 4 parts (AH,AL,BH,BL)

union Pack4 { __nv_bfloat16 h[4]; uint2 u; };

__device__ __forceinline__ void split_store(__nv_bfloat16* Hs, __nv_bfloat16* Ls,
                                            int row, int c4, float4 v) {
    float f[4] = {v.x, v.y, v.z, v.w};
    Pack4 H, L;
    #pragma unroll
    for (int i = 0; i < 4; i++) {
        __nv_bfloat16 hv = __float2bfloat16_rn(f[i]);
        H.h[i] = hv;
        L.h[i] = __float2bfloat16_rn(f[i] - __bfloat162float(hv));
    }
    *reinterpret_cast<uint2*>(Hs + row * PITCH + c4 * 4) = H.u;
    *reinterpret_cast<uint2*>(Ls + row * PITCH + c4 * 4) = L.u;
}

#define MMA_BF16(d, a, b0v, b1v)                                           \
    asm volatile("mma.sync.aligned.m16n8k16.row.col.f32.bf16.bf16.f32 "    \
        "{%0,%1,%2,%3}, {%4,%5,%6,%7}, {%8,%9}, {%0,%1,%2,%3};"            \
        : "+f"(d[0]), "+f"(d[1]), "+f"(d[2]), "+f"(d[3])                   \
        : "r"(a[0]), "r"(a[1]), "r"(a[2]), "r"(a[3]), "r"(b0v), "r"(b1v))

template <int EPI>
__global__ __launch_bounds__(512) void gemm3(
    const float* __restrict__ A, const float* __restrict__ W,
    const float* __restrict__ Res, float* __restrict__ C,
    int M, int N, int K)
{
    extern __shared__ __nv_bfloat16 sm3[];
    // parts: 0=AH 1=AL 2=BH 3=BL ; stage s at (s*4+p)*TILE3
    int tid = threadIdx.x;
    int bm = blockIdx.y * 128;
    int bn = blockIdx.x * 128;
    int wid = tid >> 5, lane = tid & 31;
    int wm = (wid & 3) * 32;      // warp m offset
    int wn = (wid >> 2) * 32;     // warp n offset
    int lt = lane >> 2, g = lane & 3;

    float acc[2][4][4];
    #pragma unroll
    for (int i = 0; i < 2; i++)
        #pragma unroll
        for (int j = 0; j < 4; j++)
            #pragma unroll
            for (int r = 0; r < 4; r++) acc[i][j][r] = 0.f;

    // --- load stage 0 ---
    {
        __nv_bfloat16* AH = sm3 + 0 * TILE3;
        __nv_bfloat16* AL = sm3 + 1 * TILE3;
        __nv_bfloat16* BH = sm3 + 2 * TILE3;
        __nv_bfloat16* BL = sm3 + 3 * TILE3;
        #pragma unroll
        for (int i = 0; i < 2; i++) {
            int idx = tid + i * 512;
            int row = idx >> 3, c4 = idx & 7;
            float4 va = *reinterpret_cast<const float4*>(&A[(size_t)(bm + row) * K + c4 * 4]);
            split_store(AH, AL, row, c4, va);
            float4 vb = *reinterpret_cast<const float4*>(&W[(size_t)(bn + row) * K + c4 * 4]);
            split_store(BH, BL, row, c4, vb);
        }
    }
    __syncthreads();

    int nstage = K / 32;
    for (int it = 0; it < nstage; it++) {
        int s = it & 1;
        // prefetch next stage into registers
        float4 pa[2], pb[2];
        bool more = (it + 1 < nstage);
        if (more) {
            int k0 = (it + 1) * 32;
            #pragma unroll
            for (int i = 0; i < 2; i++) {
                int idx = tid + i * 512;
                int row = idx >> 3, c4 = idx & 7;
                pa[i] = *reinterpret_cast<const float4*>(&A[(size_t)(bm + row) * K + k0 + c4 * 4]);
                pb[i] = *reinterpret_cast<const float4*>(&W[(size_t)(bn + row) * K + k0 + c4 * 4]);
            }
        }

        // compute on stage s
        const unsigned int* AH = reinterpret_cast<const unsigned int*>(sm3 + (s * 4 + 0) * TILE3);
        const unsigned int* AL = reinterpret_cast<const unsigned int*>(sm3 + (s * 4 + 1) * TILE3);
        const unsigned int* BH = reinterpret_cast<const unsigned int*>(sm3 + (s * 4 + 2) * TILE3);
        const unsigned int* BL = reinterpret_cast<const unsigned int*>(sm3 + (s * 4 + 3) * TILE3);

        #pragma unroll
        for (int kk2 = 0; kk2 < 2; kk2++) {
            int kw = kk2 * 8;   // word offset within row (k16 step)
            unsigned int ah[2][4], al[2][4];
            #pragma unroll
            for (int mi = 0; mi < 2; mi++) {
                int m0 = wm + mi * 16 + lt;
                int base0 = m0 * 20 + kw + g;
                int base1 = (m0 + 8) * 20 + kw + g;
                ah[mi][0] = AH[base0];
                ah[mi][1] = AH[base1];
                ah[mi][2] = AH[base0 + 4];
                ah[mi][3] = AH[base1 + 4];
                al[mi][0] = AL[base0];
                al[mi][1] = AL[base1];
                al[mi][2] = AL[base0 + 4];
                al[mi][3] = AL[base1 + 4];
            }
            #pragma unroll
            for (int ni = 0; ni < 4; ni++) {
                int n0 = wn + ni * 8 + lt;
                int nb = n0 * 20 + kw + g;
                unsigned int bh0 = BH[nb], bh1 = BH[nb + 4];
                unsigned int bl0 = BL[nb], bl1 = BL[nb + 4];
                #pragma unroll
                for (int mi = 0; mi < 2; mi++) {
                    MMA_BF16(acc[mi][ni], ah[mi], bh0, bh1);
                    MMA_BF16(acc[mi][ni], ah[mi], bl0, bl1);
                    MMA_BF16(acc[mi][ni], al[mi], bh0, bh1);
                }
            }
        }

        // store prefetched data into the other stage
        if (more) {
            int sn = s ^ 1;
            __nv_bfloat16* AHn = sm3 + (sn * 4 + 0) * TILE3;
            __nv_bfloat16* ALn = sm3 + (sn * 4 + 1) * TILE3;
            __nv_bfloat16* BHn = sm3 + (sn * 4 + 2) * TILE3;
            __nv_bfloat16* BLn = sm3 + (sn * 4 + 3) * TILE3;
            #pragma unroll
            for (int i = 0; i < 2; i++) {
                int idx = tid + i * 512;
                int row = idx >> 3, c4 = idx & 7;
                split_store(AHn, ALn, row, c4, pa[i]);
                split_store(BHn, BLn, row, c4, pb[i]);
            }
        }
        __syncthreads();
    }

    // epilogue
    #pragma unroll
    for (int mi = 0; mi < 2; mi++) {
        #pragma unroll
        for (int ni = 0; ni < 4; ni++) {
            int r0 = bm + wm + mi * 16 + lt;
            int c0 = bn + wn + ni * 8 + g * 2;
            float2 v0 = {acc[mi][ni][0], acc[mi][ni][1]};
            float2 v1 = {acc[mi][ni][2], acc[mi][ni][3]};
            if (EPI == EPI_RELU2) {
                v0.x = fmaxf(v0.x, 0.f); v0.x *= v0.x;
                v0.y = fmaxf(v0.y, 0.f); v0.y *= v0.y;
                v1.x = fmaxf(v1.x, 0.f); v1.x *= v1.x;
                v1.y = fmaxf(v1.y, 0.f); v1.y *= v1.y;
            } else if (EPI == EPI_ADD) {
                float2 r0v = *reinterpret_cast<const float2*>(&Res[(size_t)r0 * N + c0]);
                float2 r1v = *reinterpret_cast<const float2*>(&Res[(size_t)(r0 + 8) * N + c0]);
                v0.x += r0v.x; v0.y += r0v.y;
                v1.x += r1v.x; v1.y += r1v.y;
            }
            *reinterpret_cast<float2*>(&C[(size_t)r0 * N + c0]) = v0;
            *reinterpret_cast<float2*>(&C[(size_t)(r0 + 8) * N + c0]) = v1;
        }
    }
}

// ---------------------------------------------------------------------------
// Flash-style causal attention (fp32). Q/K/V layout: [B, T, H*HD]
// ---------------------------------------------------------------------------
struct AttSmem {
    float Q[64][128];
    float K[64][128];
    float V[64][128];
    float S[64][65];
    float mrow[64];
    float lrow[64];
    float arow[64];
};

extern __shared__ float att_raw[];

__global__ __launch_bounds__(256) void attn_kernel(
    const float* __restrict__ q, const float* __restrict__ k,
    const float* __restrict__ v, float* __restrict__ o)
{
    AttSmem* sm = reinterpret_cast<AttSmem*>(att_raw);
    int tid = threadIdx.x;
    int qt = blockIdx.x, h = blockIdx.y, b = blockIdx.z;
    int qbase = qt * 64;
    const float scale = 0.08838834764831845f;  // 1/sqrt(128)
    size_t base = ((size_t)b * TT) * CC + (size_t)h * HD;

    #pragma unroll
    for (int i = 0; i < 8; i++) {
        int lin = tid + i * 256;
        int r = lin >> 5;
        int c4 = (lin & 31) * 4;
        float4 vq = *reinterpret_cast<const float4*>(&q[base + (size_t)(qbase + r) * CC + c4]);
        vq.x *= scale; vq.y *= scale; vq.z *= scale; vq.w *= scale;
        *reinterpret_cast<float4*>(&sm->Q[r][c4]) = vq;
    }
    if (tid < 64) { sm->mrow[tid] = -1e30f; sm->lrow[tid] = 0.f; }

    float acc[4][8];
    #pragma unroll
    for (int i = 0; i < 4; i++)
        #pragma unroll
        for (int j = 0; j < 8; j++) acc[i][j] = 0.f;

    int mt = tid >> 4;
    int dt = tid & 15;
    __syncthreads();

    for (int nt = 0; nt <= qt; nt++) {
        int kbase = nt * 64;
        #pragma unroll
        for (int i = 0; i < 8; i++) {
            int lin = tid + i * 256;
            int r = lin >> 5;
            int c4 = (lin & 31) * 4;
            *reinterpret_cast<float4*>(&sm->K[r][c4]) =
                *reinterpret_cast<const float4*>(&k[base + (size_t)(kbase + r) * CC + c4]);
            *reinterpret_cast<float4*>(&sm->V[r][c4]) =
                *reinterpret_cast<const float4*>(&v[base + (size_t)(kbase + r) * CC + c4]);
        }
        __syncthreads();

        {
            int r0 = (tid >> 4) * 4, c0 = (tid & 15) * 4;
            float s[4][4];
            #pragma unroll
            for (int i = 0; i < 4; i++)
                #pragma unroll
                for (int j = 0; j < 4; j++) s[i][j] = 0.f;
            for (int d = 0; d < 128; d++) {
                float a0 = sm->Q[r0 + 0][d], a1 = sm->Q[r0 + 1][d];
                float a2 = sm->Q[r0 + 2][d], a3 = sm->Q[r0 + 3][d];
                float b0 = sm->K[c0 + 0][d], b1 = sm->K[c0 + 1][d];
                float b2 = sm->K[c0 + 2][d], b3 = sm->K[c0 + 3][d];
                s[0][0] = fmaf(a0, b0, s[0][0]); s[0][1] = fmaf(a0, b1, s[0][1]);
                s[0][2] = fmaf(a0, b2, s[0][2]); s[0][3] = fmaf(a0, b3, s[0][3]);
                s[1][0] = fmaf(a1, b0, s[1][0]); s[1][1] = fmaf(a1, b1, s[1][1]);
                s[1][2] = fmaf(a1, b2, s[1][2]); s[1][3] = fmaf(a1, b3, s[1][3]);
                s[2][0] = fmaf(a2, b0, s[2][0]); s[2][1] = fmaf(a2, b1, s[2][1]);
                s[2][2] = fmaf(a2, b2, s[2][2]); s[2][3] = fmaf(a2, b3, s[2][3]);
                s[3][0] = fmaf(a3, b0, s[3][0]); s[3][1] = fmaf(a3, b1, s[3][1]);
                s[3][2] = fmaf(a3, b2, s[3][2]); s[3][3] = fmaf(a3, b3, s[3][3]);
            }
            #pragma unroll
            for (int i = 0; i < 4; i++)
                #pragma unroll
                for (int j = 0; j < 4; j++) {
                    int kg = kbase + c0 + j, qg = qbase + r0 + i;
                    sm->S[r0 + i][c0 + j] = (kg <= qg) ? s[i][j] : -1e30f;
                }
        }
        __syncthreads();

        {
            int row = tid >> 2, sub = tid & 3;
            float tmax = -1e30f;
            #pragma unroll
            for (int c = 0; c < 16; c++) tmax = fmaxf(tmax, sm->S[row][sub * 16 + c]);
            tmax = fmaxf(tmax, __shfl_xor_sync(0xffffffffu, tmax, 1));
            tmax = fmaxf(tmax, __shfl_xor_sync(0xffffffffu, tmax, 2));
            float mprev = sm->mrow[row];
            float newm = fmaxf(mprev, tmax);
            float ls = 0.f;
            #pragma unroll
            for (int c = 0; c < 16; c++) {
                float p = __expf(sm->S[row][sub * 16 + c] - newm);
                sm->S[row][sub * 16 + c] = p;
                ls += p;
            }
            ls += __shfl_xor_sync(0xffffffffu, ls, 1);
            ls += __shfl_xor_sync(0xffffffffu, ls, 2);
            if (sub == 0) {
                float al = __expf(mprev - newm);
                sm->mrow[row] = newm;
                sm->lrow[row] = sm->lrow[row] * al + ls;
                sm->arow[row] = al;
            }
        }
        __syncthreads();

        #pragma unroll
        for (int i = 0; i < 4; i++) {
            float al = sm->arow[mt * 4 + i];
            #pragma unroll
            for (int j = 0; j < 8; j++) acc[i][j] *= al;
        }
        for (int kk = 0; kk < 64; kk++) {
            float4 v0 = *reinterpret_cast<const float4*>(&sm->V[kk][dt * 8]);
            float4 v1 = *reinterpret_cast<const float4*>(&sm->V[kk][dt * 8 + 4]);
            float vv[8] = {v0.x, v0.y, v0.z, v0.w, v1.x, v1.y, v1.z, v1.w};
            #pragma unroll
            for (int i = 0; i < 4; i++) {
                float p = sm->S[mt * 4 + i][kk];
                #pragma unroll
                for (int j = 0; j < 8; j++) acc[i][j] = fmaf(p, vv[j], acc[i][j]);
            }
        }
        __syncthreads();
    }

    #pragma unroll
    for (int i = 0; i < 4; i++) {
        int rm = mt * 4 + i;
        float inv = 1.f / sm->lrow[rm];
        float4 o0, o1;
        o0.x = acc[i][0] * inv; o0.y = acc[i][1] * inv;
        o0.z = acc[i][2] * inv; o0.w = acc[i][3] * inv;
        o1.x = acc[i][4] * inv; o1.y = acc[i][5] * inv;
        o1.z = acc[i][6] * inv; o1.w = acc[i][7] * inv;
        size_t obase = base + (size_t)(qbase + rm) * CC + dt * 8;
        *reinterpret_cast<float4*>(&o[obase]) = o0;
        *reinterpret_cast<float4*>(&o[obase + 4]) = o1;
    }
}

// ---------------------------------------------------------------------------
// Launch
// ---------------------------------------------------------------------------
extern "C" void kernel_launch(void* const* d_in, const int* in_sizes, int n_in,
                              void* d_out, int out_size) {
    const float* x   = (const float*)d_in[0];
    const float* wq  = (const float*)d_in[1];
    const float* wk  = (const float*)d_in[2];
    const float* wv  = (const float*)d_in[3];
    const float* wo  = (const float*)d_in[4];
    const float* fc1 = (const float*)d_in[5];
    const float* fc2 = (const float*)d_in[6];
    float* out = (float*)d_out;

    float *h, *q, *k, *v, *att, *x1, *m;
    cudaGetSymbolAddress((void**)&h,   g_h);
    cudaGetSymbolAddress((void**)&q,   g_q);
    cudaGetSymbolAddress((void**)&k,   g_k);
    cudaGetSymbolAddress((void**)&v,   g_v);
    cudaGetSymbolAddress((void**)&att, g_att);
    cudaGetSymbolAddress((void**)&x1,  g_x1);
    cudaGetSymbolAddress((void**)&m,   g_m);

    static_assert(sizeof(AttSmem) <= 120 * 1024, "smem");
    cudaFuncSetAttribute(attn_kernel, cudaFuncAttributeMaxDynamicSharedMemorySize,
                         (int)sizeof(AttSmem));
    cudaFuncSetAttribute(gemm3<EPI_NONE>, cudaFuncAttributeMaxDynamicSharedMemorySize, SMEM3);
    cudaFuncSetAttribute(gemm3<EPI_ADD>,  cudaFuncAttributeMaxDynamicSharedMemorySize, SMEM3);
    cudaFuncSetAttribute(gemm3<EPI_RELU2>, cudaFuncAttributeMaxDynamicSharedMemorySize, SMEM3);

    dim3 thr(512);

    // 1) h = rmsnorm(x)
    rmsnorm_kernel<<<BT, 256>>>(x, h);

    // 2-4) q,k,v = h @ w{q,k,v}^T
    dim3 g_qkv(CC / 128, BT / 128);
    gemm3<EPI_NONE><<<g_qkv, thr, SMEM3>>>(h, wq, nullptr, q, BT, CC, CC);
    gemm3<EPI_NONE><<<g_qkv, thr, SMEM3>>>(h, wk, nullptr, k, BT, CC, CC);
    gemm3<EPI_NONE><<<g_qkv, thr, SMEM3>>>(h, wv, nullptr, v, BT, CC, CC);

    // 5) causal attention
    dim3 g_att_grid(TT / 64, HH, BB);
    attn_kernel<<<g_att_grid, 256, sizeof(AttSmem)>>>(q, k, v, att);

    // 6) x1 = x + att @ wo^T
    gemm3<EPI_ADD><<<g_qkv, thr, SMEM3>>>(att, wo, x, x1, BT, CC, CC);

    // 7) h = rmsnorm(x1)
    rmsnorm_kernel<<<BT, 256>>>(x1, h);

    // 8) m = relu(h @ fc1^T)^2
    dim3 g_fc1(MLPD / 128, BT / 128);
    gemm3<EPI_RELU2><<<g_fc1, thr, SMEM3>>>(h, fc1, nullptr, m, BT, MLPD, CC);

    // 9) out = x1 + m @ fc2^T
    dim3 g_fc2(CC / 128, BT / 128);
    gemm3<EPI_ADD><<<g_fc2, thr, SMEM3>>>(m, fc2, x1, out, BT, CC, MLPD);
}

// round 9
// speedup vs baseline: 2.4839x; 1.5492x over previous
#include <cuda_runtime.h>
#include <cuda_bf16.h>
#include <cstdint>
#include <stdint.h>
#include <math.h>

// Problem constants
#define BB 2
#define TT 2048
#define CC 2048
#define HH 16
#define HD 128
#define MLPD 8192
#define BT (BB*TT)          // 4096 rows
#define EPS 1e-5f

// ---------------------------------------------------------------------------
// Scratch (device globals; no allocations allowed)
// ---------------------------------------------------------------------------
__device__ float g_h[(size_t)BT*CC];     // rmsnorm output
__device__ float g_q[(size_t)BT*CC];
__device__ float g_k[(size_t)BT*CC];
__device__ float g_v[(size_t)BT*CC];
__device__ float g_att[(size_t)BT*CC];   // attention output (pre-proj)
__device__ float g_x1[(size_t)BT*CC];    // x after attention residual
__device__ float g_m[(size_t)BT*MLPD];   // MLP hidden

// ---------------------------------------------------------------------------
// RMSNorm: one block per row
// ---------------------------------------------------------------------------
__global__ void rmsnorm_kernel(const float* __restrict__ x, float* __restrict__ o) {
    int row = blockIdx.x;
    const float* xr = x + (size_t)row * CC;
    float ss = 0.f;
    for (int c = threadIdx.x; c < CC; c += blockDim.x) {
        float vv = xr[c];
        ss += vv * vv;
    }
    __shared__ float red[32];
    #pragma unroll
    for (int off = 16; off; off >>= 1) ss += __shfl_xor_sync(0xffffffffu, ss, off);
    int wid = threadIdx.x >> 5, lane = threadIdx.x & 31;
    if (lane == 0) red[wid] = ss;
    __syncthreads();
    if (wid == 0) {
        float v2 = lane < (blockDim.x >> 5) ? red[lane] : 0.f;
        #pragma unroll
        for (int off = 16; off; off >>= 1) v2 += __shfl_xor_sync(0xffffffffu, v2, off);
        if (lane == 0) red[0] = rsqrtf(v2 / (float)CC + EPS);
    }
    __syncthreads();
    float r = red[0];
    float* orow = o + (size_t)row * CC;
    for (int c = threadIdx.x; c < CC; c += blockDim.x) orow[c] = xr[c] * r;
}

// ---------------------------------------------------------------------------
// Shared helpers
// ---------------------------------------------------------------------------
union Pack4 { __nv_bfloat16 h[4]; uint2 u; };

#define MMA_BF16(d, a, b0v, b1v)                                           \
    asm volatile("mma.sync.aligned.m16n8k16.row.col.f32.bf16.bf16.f32 "    \
        "{%0,%1,%2,%3}, {%4,%5,%6,%7}, {%8,%9}, {%0,%1,%2,%3};"            \
        : "+f"(d[0]), "+f"(d[1]), "+f"(d[2]), "+f"(d[3])                   \
        : "r"(a[0]), "r"(a[1]), "r"(a[2]), "r"(a[3]), "r"(b0v), "r"(b1v))

// ---------------------------------------------------------------------------
// bf16x3 split-precision GEMM via mma.sync.m16n8k16  (identical to R5 passing)
// ---------------------------------------------------------------------------
enum { EPI_NONE = 0, EPI_ADD = 1, EPI_RELU2 = 2 };

#define PITCH 40            // bf16 elems per smem row (32 + 8 pad); 20 words
#define TILE3 (128*PITCH)   // bf16 elems per tile part
#define SMEM3 (2*4*TILE3*2) // bytes: 2 stages x 4 parts (AH,AL,BH,BL)

__device__ __forceinline__ void split_store(__nv_bfloat16* Hs, __nv_bfloat16* Ls,
                                            int row, int c4, float4 v) {
    float f[4] = {v.x, v.y, v.z, v.w};
    Pack4 H, L;
    #pragma unroll
    for (int i = 0; i < 4; i++) {
        __nv_bfloat16 hv = __float2bfloat16_rn(f[i]);
        H.h[i] = hv;
        L.h[i] = __float2bfloat16_rn(f[i] - __bfloat162float(hv));
    }
    *reinterpret_cast<uint2*>(Hs + row * PITCH + c4 * 4) = H.u;
    *reinterpret_cast<uint2*>(Ls + row * PITCH + c4 * 4) = L.u;
}

template <int EPI>
__global__ __launch_bounds__(512) void gemm3(
    const float* __restrict__ A, const float* __restrict__ W,
    const float* __restrict__ Res, float* __restrict__ C,
    int M, int N, int K)
{
    extern __shared__ __nv_bfloat16 sm3[];
    int tid = threadIdx.x;
    int bm = blockIdx.y * 128;
    int bn = blockIdx.x * 128;
    int wid = tid >> 5, lane = tid & 31;
    int wm = (wid & 3) * 32;      // warp m offset
    int wn = (wid >> 2) * 32;     // warp n offset
    int lt = lane >> 2, g = lane & 3;

    float acc[2][4][4];
    #pragma unroll
    for (int i = 0; i < 2; i++)
        #pragma unroll
        for (int j = 0; j < 4; j++)
            #pragma unroll
            for (int r = 0; r < 4; r++) acc[i][j][r] = 0.f;

    {
        __nv_bfloat16* AH = sm3 + 0 * TILE3;
        __nv_bfloat16* AL = sm3 + 1 * TILE3;
        __nv_bfloat16* BH = sm3 + 2 * TILE3;
        __nv_bfloat16* BL = sm3 + 3 * TILE3;
        #pragma unroll
        for (int i = 0; i < 2; i++) {
            int idx = tid + i * 512;
            int row = idx >> 3, c4 = idx & 7;
            float4 va = *reinterpret_cast<const float4*>(&A[(size_t)(bm + row) * K + c4 * 4]);
            split_store(AH, AL, row, c4, va);
            float4 vb = *reinterpret_cast<const float4*>(&W[(size_t)(bn + row) * K + c4 * 4]);
            split_store(BH, BL, row, c4, vb);
        }
    }
    __syncthreads();

    int nstage = K / 32;
    for (int it = 0; it < nstage; it++) {
        int s = it & 1;
        float4 pa[2], pb[2];
        bool more = (it + 1 < nstage);
        if (more) {
            int k0 = (it + 1) * 32;
            #pragma unroll
            for (int i = 0; i < 2; i++) {
                int idx = tid + i * 512;
                int row = idx >> 3, c4 = idx & 7;
                pa[i] = *reinterpret_cast<const float4*>(&A[(size_t)(bm + row) * K + k0 + c4 * 4]);
                pb[i] = *reinterpret_cast<const float4*>(&W[(size_t)(bn + row) * K + k0 + c4 * 4]);
            }
        }

        const unsigned int* AH = reinterpret_cast<const unsigned int*>(sm3 + (s * 4 + 0) * TILE3);
        const unsigned int* AL = reinterpret_cast<const unsigned int*>(sm3 + (s * 4 + 1) * TILE3);
        const unsigned int* BH = reinterpret_cast<const unsigned int*>(sm3 + (s * 4 + 2) * TILE3);
        const unsigned int* BL = reinterpret_cast<const unsigned int*>(sm3 + (s * 4 + 3) * TILE3);

        #pragma unroll
        for (int kk2 = 0; kk2 < 2; kk2++) {
            int kw = kk2 * 8;
            unsigned int ah[2][4], al[2][4];
            #pragma unroll
            for (int mi = 0; mi < 2; mi++) {
                int m0 = wm + mi * 16 + lt;
                int base0 = m0 * 20 + kw + g;
                int base1 = (m0 + 8) * 20 + kw + g;
                ah[mi][0] = AH[base0];
                ah[mi][1] = AH[base1];
                ah[mi][2] = AH[base0 + 4];
                ah[mi][3] = AH[base1 + 4];
                al[mi][0] = AL[base0];
                al[mi][1] = AL[base1];
                al[mi][2] = AL[base0 + 4];
                al[mi][3] = AL[base1 + 4];
            }
            #pragma unroll
            for (int ni = 0; ni < 4; ni++) {
                int n0 = wn + ni * 8 + lt;
                int nb = n0 * 20 + kw + g;
                unsigned int bh0 = BH[nb], bh1 = BH[nb + 4];
                unsigned int bl0 = BL[nb], bl1 = BL[nb + 4];
                #pragma unroll
                for (int mi = 0; mi < 2; mi++) {
                    MMA_BF16(acc[mi][ni], ah[mi], bh0, bh1);
                    MMA_BF16(acc[mi][ni], ah[mi], bl0, bl1);
                    MMA_BF16(acc[mi][ni], al[mi], bh0, bh1);
                }
            }
        }

        if (more) {
            int sn = s ^ 1;
            __nv_bfloat16* AHn = sm3 + (sn * 4 + 0) * TILE3;
            __nv_bfloat16* ALn = sm3 + (sn * 4 + 1) * TILE3;
            __nv_bfloat16* BHn = sm3 + (sn * 4 + 2) * TILE3;
            __nv_bfloat16* BLn = sm3 + (sn * 4 + 3) * TILE3;
            #pragma unroll
            for (int i = 0; i < 2; i++) {
                int idx = tid + i * 512;
                int row = idx >> 3, c4 = idx & 7;
                split_store(AHn, ALn, row, c4, pa[i]);
                split_store(BHn, BLn, row, c4, pb[i]);
            }
        }
        __syncthreads();
    }

    #pragma unroll
    for (int mi = 0; mi < 2; mi++) {
        #pragma unroll
        for (int ni = 0; ni < 4; ni++) {
            int r0 = bm + wm + mi * 16 + lt;
            int c0 = bn + wn + ni * 8 + g * 2;
            float2 v0 = {acc[mi][ni][0], acc[mi][ni][1]};
            float2 v1 = {acc[mi][ni][2], acc[mi][ni][3]};
            if (EPI == EPI_RELU2) {
                v0.x = fmaxf(v0.x, 0.f); v0.x *= v0.x;
                v0.y = fmaxf(v0.y, 0.f); v0.y *= v0.y;
                v1.x = fmaxf(v1.x, 0.f); v1.x *= v1.x;
                v1.y = fmaxf(v1.y, 0.f); v1.y *= v1.y;
            } else if (EPI == EPI_ADD) {
                float2 r0v = *reinterpret_cast<const float2*>(&Res[(size_t)r0 * N + c0]);
                float2 r1v = *reinterpret_cast<const float2*>(&Res[(size_t)(r0 + 8) * N + c0]);
                v0.x += r0v.x; v0.y += r0v.y;
                v1.x += r1v.x; v1.y += r1v.y;
            }
            *reinterpret_cast<float2*>(&C[(size_t)r0 * N + c0]) = v0;
            *reinterpret_cast<float2*>(&C[(size_t)(r0 + 8) * N + c0]) = v1;
        }
    }
}

// ---------------------------------------------------------------------------
// bf16x3 flash attention via mma.sync. BM=64 (4 warps x 16 rows), BN=64.
// Q/K smem: [row][128] bf16 hi+lo, pitch 136 (68 words).
// V smem: transposed [d][key] bf16 hi+lo, pitch 72 (36 words).
// S = QK^T and O += PV each use 3 split MMAs; softmax state in registers.
// ---------------------------------------------------------------------------
// bf16-unit offsets
#define AQH 0
#define AQL 8704
#define AKH 17408
#define AKL 26112
#define AVH 34816
#define AVL 44032
#define ATT_SMEM 106496   // bytes (53248 bf16)
// word offsets (uint32 units)
#define WQH 0
#define WQL 4352
#define WKH 8704
#define WKL 13056
#define WVH 17408
#define WVL 22016

__device__ __forceinline__ void split_pack2(float x, float y,
                                            unsigned int& hi, unsigned int& lo) {
    __nv_bfloat16 xh = __float2bfloat16_rn(x);
    __nv_bfloat16 yh = __float2bfloat16_rn(y);
    __nv_bfloat16 xl = __float2bfloat16_rn(x - __bfloat162float(xh));
    __nv_bfloat16 yl = __float2bfloat16_rn(y - __bfloat162float(yh));
    hi = (unsigned int)__bfloat16_as_ushort(xh) |
         ((unsigned int)__bfloat16_as_ushort(yh) << 16);
    lo = (unsigned int)__bfloat16_as_ushort(xl) |
         ((unsigned int)__bfloat16_as_ushort(yl) << 16);
}

__global__ __launch_bounds__(128) void attn_mma(
    const float* __restrict__ q, const float* __restrict__ k,
    const float* __restrict__ v, float* __restrict__ o)
{
    extern __shared__ char attsm[];
    __nv_bfloat16* sb = reinterpret_cast<__nv_bfloat16*>(attsm);
    unsigned int* s32 = reinterpret_cast<unsigned int*>(attsm);

    int tid = threadIdx.x;
    int wid = tid >> 5, lane = tid & 31;
    int lt = lane >> 2, g = lane & 3;
    int wrow = wid * 16;
    int qt = blockIdx.x, h = blockIdx.y, b = blockIdx.z;
    int qb = qt * 64;
    const float scale = 0.08838834764831845f;  // 1/sqrt(128)
    size_t base = ((size_t)b * TT) * CC + (size_t)h * HD;

    // ---- load Q (scaled, split) once ----
    #pragma unroll
    for (int i = 0; i < 16; i++) {
        int lin = tid + i * 128;
        int r = lin >> 5, c4 = (lin & 31) * 4;
        float4 vq = *reinterpret_cast<const float4*>(&q[base + (size_t)(qb + r) * CC + c4]);
        float f[4] = {vq.x * scale, vq.y * scale, vq.z * scale, vq.w * scale};
        Pack4 H, L;
        #pragma unroll
        for (int j = 0; j < 4; j++) {
            __nv_bfloat16 hv = __float2bfloat16_rn(f[j]);
            H.h[j] = hv;
            L.h[j] = __float2bfloat16_rn(f[j] - __bfloat162float(hv));
        }
        *reinterpret_cast<uint2*>(&sb[AQH + r * 136 + c4]) = H.u;
        *reinterpret_cast<uint2*>(&sb[AQL + r * 136 + c4]) = L.u;
    }

    float oacc[16][4];
    #pragma unroll
    for (int i = 0; i < 16; i++)
        #pragma unroll
        for (int j = 0; j < 4; j++) oacc[i][j] = 0.f;
    float m0 = -1e30f, m1 = -1e30f, l0 = 0.f, l1 = 0.f;

    for (int nt = 0; nt <= qt; nt++) {
        int kb = nt * 64;
        // ---- load K (split) ----
        #pragma unroll
        for (int i = 0; i < 16; i++) {
            int lin = tid + i * 128;
            int r = lin >> 5, c4 = (lin & 31) * 4;
            float4 vk = *reinterpret_cast<const float4*>(&k[base + (size_t)(kb + r) * CC + c4]);
            float f[4] = {vk.x, vk.y, vk.z, vk.w};
            Pack4 H, L;
            #pragma unroll
            for (int j = 0; j < 4; j++) {
                __nv_bfloat16 hv = __float2bfloat16_rn(f[j]);
                H.h[j] = hv;
                L.h[j] = __float2bfloat16_rn(f[j] - __bfloat162float(hv));
            }
            *reinterpret_cast<uint2*>(&sb[AKH + r * 136 + c4]) = H.u;
            *reinterpret_cast<uint2*>(&sb[AKL + r * 136 + c4]) = L.u;
        }
        // ---- load V transposed (split): Vt[d][key] ----
        #pragma unroll
        for (int i = 0; i < 16; i++) {
            int lin = tid + i * 128;
            int r = lin & 63;
            int c4 = ((lin >> 6) & 31) * 4;
            float4 vv = *reinterpret_cast<const float4*>(&v[base + (size_t)(kb + r) * CC + c4]);
            float f[4] = {vv.x, vv.y, vv.z, vv.w};
            #pragma unroll
            for (int j = 0; j < 4; j++) {
                __nv_bfloat16 hv = __float2bfloat16_rn(f[j]);
                sb[AVH + (c4 + j) * 72 + r] = hv;
                sb[AVL + (c4 + j) * 72 + r] = __float2bfloat16_rn(f[j] - __bfloat162float(hv));
            }
        }
        __syncthreads();

        // ---- S = Q K^T (bf16x3) ----
        float sacc[8][4];
        #pragma unroll
        for (int i = 0; i < 8; i++)
            #pragma unroll
            for (int j = 0; j < 4; j++) sacc[i][j] = 0.f;

        #pragma unroll
        for (int ks = 0; ks < 8; ks++) {
            unsigned int aH[4], aL[4];
            int ab = (wrow + lt) * 68 + ks * 8 + g;
            aH[0] = s32[WQH + ab];       aH[1] = s32[WQH + ab + 544];
            aH[2] = s32[WQH + ab + 4];   aH[3] = s32[WQH + ab + 548];
            aL[0] = s32[WQL + ab];       aL[1] = s32[WQL + ab + 544];
            aL[2] = s32[WQL + ab + 4];   aL[3] = s32[WQL + ab + 548];
            #pragma unroll
            for (int ni = 0; ni < 8; ni++) {
                int bb = (ni * 8 + lt) * 68 + ks * 8 + g;
                unsigned int bh0 = s32[WKH + bb], bh1 = s32[WKH + bb + 4];
                unsigned int bl0 = s32[WKL + bb], bl1 = s32[WKL + bb + 4];
                MMA_BF16(sacc[ni], aH, bh0, bh1);
                MMA_BF16(sacc[ni], aH, bl0, bl1);
                MMA_BF16(sacc[ni], aL, bh0, bh1);
            }
        }

        // ---- causal mask (diagonal tile only) ----
        if (nt == qt) {
            int row0 = qb + wrow + lt, row1 = row0 + 8;
            #pragma unroll
            for (int ni = 0; ni < 8; ni++) {
                int c0 = kb + ni * 8 + 2 * g;
                if (c0 > row0)     sacc[ni][0] = -1e30f;
                if (c0 + 1 > row0) sacc[ni][1] = -1e30f;
                if (c0 > row1)     sacc[ni][2] = -1e30f;
                if (c0 + 1 > row1) sacc[ni][3] = -1e30f;
            }
        }

        // ---- online softmax (registers) ----
        float rm0 = -1e30f, rm1 = -1e30f;
        #pragma unroll
        for (int ni = 0; ni < 8; ni++) {
            rm0 = fmaxf(rm0, fmaxf(sacc[ni][0], sacc[ni][1]));
            rm1 = fmaxf(rm1, fmaxf(sacc[ni][2], sacc[ni][3]));
        }
        rm0 = fmaxf(rm0, __shfl_xor_sync(0xffffffffu, rm0, 1));
        rm0 = fmaxf(rm0, __shfl_xor_sync(0xffffffffu, rm0, 2));
        rm1 = fmaxf(rm1, __shfl_xor_sync(0xffffffffu, rm1, 1));
        rm1 = fmaxf(rm1, __shfl_xor_sync(0xffffffffu, rm1, 2));
        float mn0 = fmaxf(m0, rm0), mn1 = fmaxf(m1, rm1);
        float al0 = __expf(m0 - mn0), al1 = __expf(m1 - mn1);
        m0 = mn0; m1 = mn1;
        float rs0 = 0.f, rs1 = 0.f;
        #pragma unroll
        for (int ni = 0; ni < 8; ni++) {
            sacc[ni][0] = __expf(sacc[ni][0] - m0);
            sacc[ni][1] = __expf(sacc[ni][1] - m0);
            sacc[ni][2] = __expf(sacc[ni][2] - m1);
            sacc[ni][3] = __expf(sacc[ni][3] - m1);
            rs0 += sacc[ni][0] + sacc[ni][1];
            rs1 += sacc[ni][2] + sacc[ni][3];
        }
        l0 = l0 * al0 + rs0;
        l1 = l1 * al1 + rs1;
        #pragma unroll
        for (int ni = 0; ni < 16; ni++) {
            oacc[ni][0] *= al0; oacc[ni][1] *= al0;
            oacc[ni][2] *= al1; oacc[ni][3] *= al1;
        }

        // ---- O += P V (bf16x3, P from registers) ----
        #pragma unroll
        for (int kk = 0; kk < 4; kk++) {
            unsigned int pH[4], pL[4];
            split_pack2(sacc[2 * kk][0],     sacc[2 * kk][1],     pH[0], pL[0]);
            split_pack2(sacc[2 * kk][2],     sacc[2 * kk][3],     pH[1], pL[1]);
            split_pack2(sacc[2 * kk + 1][0], sacc[2 * kk + 1][1], pH[2], pL[2]);
            split_pack2(sacc[2 * kk + 1][2], sacc[2 * kk + 1][3], pH[3], pL[3]);
            #pragma unroll
            for (int ni = 0; ni < 16; ni++) {
                int vb2 = (ni * 8 + lt) * 36 + kk * 8 + g;
                unsigned int vh0 = s32[WVH + vb2], vh1 = s32[WVH + vb2 + 4];
                unsigned int vl0 = s32[WVL + vb2], vl1 = s32[WVL + vb2 + 4];
                MMA_BF16(oacc[ni], pH, vh0, vh1);
                MMA_BF16(oacc[ni], pH, vl0, vl1);
                MMA_BF16(oacc[ni], pL, vh0, vh1);
            }
        }
        __syncthreads();
    }

    // ---- finalize: l reduce across quad, write O ----
    l0 += __shfl_xor_sync(0xffffffffu, l0, 1);
    l0 += __shfl_xor_sync(0xffffffffu, l0, 2);
    l1 += __shfl_xor_sync(0xffffffffu, l1, 1);
    l1 += __shfl_xor_sync(0xffffffffu, l1, 2);
    float inv0 = 1.f / l0, inv1 = 1.f / l1;
    int row0 = qb + wrow + lt;
    #pragma unroll
    for (int ni = 0; ni < 16; ni++) {
        size_t o0 = base + (size_t)row0 * CC + ni * 8 + 2 * g;
        float2 w0 = {oacc[ni][0] * inv0, oacc[ni][1] * inv0};
        float2 w1 = {oacc[ni][2] * inv1, oacc[ni][3] * inv1};
        *reinterpret_cast<float2*>(&o[o0]) = w0;
        *reinterpret_cast<float2*>(&o[o0 + (size_t)8 * CC]) = w1;
    }
}

// ---------------------------------------------------------------------------
// Launch
// ---------------------------------------------------------------------------
extern "C" void kernel_launch(void* const* d_in, const int* in_sizes, int n_in,
                              void* d_out, int out_size) {
    const float* x   = (const float*)d_in[0];
    const float* wq  = (const float*)d_in[1];
    const float* wk  = (const float*)d_in[2];
    const float* wv  = (const float*)d_in[3];
    const float* wo  = (const float*)d_in[4];
    const float* fc1 = (const float*)d_in[5];
    const float* fc2 = (const float*)d_in[6];
    float* out = (float*)d_out;

    float *h, *q, *k, *v, *att, *x1, *m;
    cudaGetSymbolAddress((void**)&h,   g_h);
    cudaGetSymbolAddress((void**)&q,   g_q);
    cudaGetSymbolAddress((void**)&k,   g_k);
    cudaGetSymbolAddress((void**)&v,   g_v);
    cudaGetSymbolAddress((void**)&att, g_att);
    cudaGetSymbolAddress((void**)&x1,  g_x1);
    cudaGetSymbolAddress((void**)&m,   g_m);

    cudaFuncSetAttribute(attn_mma, cudaFuncAttributeMaxDynamicSharedMemorySize, ATT_SMEM);
    cudaFuncSetAttribute(gemm3<EPI_NONE>,  cudaFuncAttributeMaxDynamicSharedMemorySize, SMEM3);
    cudaFuncSetAttribute(gemm3<EPI_ADD>,   cudaFuncAttributeMaxDynamicSharedMemorySize, SMEM3);
    cudaFuncSetAttribute(gemm3<EPI_RELU2>, cudaFuncAttributeMaxDynamicSharedMemorySize, SMEM3);

    dim3 thr(512);

    // 1) h = rmsnorm(x)
    rmsnorm_kernel<<<BT, 256>>>(x, h);

    // 2-4) q,k,v = h @ w{q,k,v}^T
    dim3 g_qkv(CC / 128, BT / 128);
    gemm3<EPI_NONE><<<g_qkv, thr, SMEM3>>>(h, wq, nullptr, q, BT, CC, CC);
    gemm3<EPI_NONE><<<g_qkv, thr, SMEM3>>>(h, wk, nullptr, k, BT, CC, CC);
    gemm3<EPI_NONE><<<g_qkv, thr, SMEM3>>>(h, wv, nullptr, v, BT, CC, CC);

    // 5) causal attention (bf16x3 mma)
    dim3 g_att_grid(TT / 64, HH, BB);
    attn_mma<<<g_att_grid, 128, ATT_SMEM>>>(q, k, v, att);

    // 6) x1 = x + att @ wo^T
    gemm3<EPI_ADD><<<g_qkv, thr, SMEM3>>>(att, wo, x, x1, BT, CC, CC);

    // 7) h = rmsnorm(x1)
    rmsnorm_kernel<<<BT, 256>>>(x1, h);

    // 8) m = relu(h @ fc1^T)^2
    dim3 g_fc1(MLPD / 128, BT / 128);
    gemm3<EPI_RELU2><<<g_fc1, thr, SMEM3>>>(h, fc1, nullptr, m, BT, MLPD, CC);

    // 9) out = x1 + m @ fc2^T
    dim3 g_fc2(CC / 128, BT / 128);
    gemm3<EPI_ADD><<<g_fc2, thr, SMEM3>>>(m, fc2, x1, out, BT, CC, MLPD);
}

// round 10
// speedup vs baseline: 2.6777x; 1.0780x over previous
#include <cuda_runtime.h>
#include <cuda_bf16.h>
#include <cstdint>
#include <stdint.h>
#include <math.h>

// Problem constants
#define BB 2
#define TT 2048
#define CC 2048
#define HH 16
#define HD 128
#define MLPD 8192
#define BT (BB*TT)          // 4096 rows
#define EPS 1e-5f

// ---------------------------------------------------------------------------
// Scratch (device globals; no allocations allowed)
// ---------------------------------------------------------------------------
__device__ float g_q[(size_t)BT*CC];
__device__ float g_k[(size_t)BT*CC];
__device__ float g_v[(size_t)BT*CC];
__device__ float g_x1[(size_t)BT*CC];

// bf16 hi/lo split operands
__device__ __nv_bfloat16 g_hH[(size_t)BT*CC],  g_hL[(size_t)BT*CC];
__device__ __nv_bfloat16 g_attH[(size_t)BT*CC], g_attL[(size_t)BT*CC];
__device__ __nv_bfloat16 g_mH[(size_t)BT*MLPD], g_mL[(size_t)BT*MLPD];
__device__ __nv_bfloat16 g_wqH[(size_t)CC*CC],  g_wqL[(size_t)CC*CC];
__device__ __nv_bfloat16 g_wkH[(size_t)CC*CC],  g_wkL[(size_t)CC*CC];
__device__ __nv_bfloat16 g_wvH[(size_t)CC*CC],  g_wvL[(size_t)CC*CC];
__device__ __nv_bfloat16 g_woH[(size_t)CC*CC],  g_woL[(size_t)CC*CC];
__device__ __nv_bfloat16 g_fc1H[(size_t)MLPD*CC], g_fc1L[(size_t)MLPD*CC];
__device__ __nv_bfloat16 g_fc2H[(size_t)MLPD*CC], g_fc2L[(size_t)MLPD*CC];

// ---------------------------------------------------------------------------
// Helpers
// ---------------------------------------------------------------------------
union Pack4 { __nv_bfloat16 h[4]; uint2 u; };

__device__ __forceinline__ uint32_t smem_u32(const void* p) {
    uint32_t a;
    asm("{ .reg .u64 t; cvta.to.shared.u64 t, %1; cvt.u32.u64 %0, t; }" : "=r"(a) : "l"(p));
    return a;
}

__device__ __forceinline__ void cpasync16(uint32_t dst, const void* src) {
    asm volatile("cp.async.cg.shared.global [%0], [%1], 16;" :: "r"(dst), "l"(src));
}
#define CP_COMMIT() asm volatile("cp.async.commit_group;" ::: "memory")
#define CP_WAIT(n)  asm volatile("cp.async.wait_group %0;" :: "n"(n) : "memory")

#define MMA_BF16(d, a, b0v, b1v)                                           \
    asm volatile("mma.sync.aligned.m16n8k16.row.col.f32.bf16.bf16.f32 "    \
        "{%0,%1,%2,%3}, {%4,%5,%6,%7}, {%8,%9}, {%0,%1,%2,%3};"            \
        : "+f"(d[0]), "+f"(d[1]), "+f"(d[2]), "+f"(d[3])                   \
        : "r"(a[0]), "r"(a[1]), "r"(a[2]), "r"(a[3]), "r"(b0v), "r"(b1v))

__device__ __forceinline__ void split_pack2(float x, float y,
                                            unsigned int& hi, unsigned int& lo) {
    __nv_bfloat16 xh = __float2bfloat16_rn(x);
    __nv_bfloat16 yh = __float2bfloat16_rn(y);
    __nv_bfloat16 xl = __float2bfloat16_rn(x - __bfloat162float(xh));
    __nv_bfloat16 yl = __float2bfloat16_rn(y - __bfloat162float(yh));
    hi = (unsigned int)__bfloat16_as_ushort(xh) |
         ((unsigned int)__bfloat16_as_ushort(yh) << 16);
    lo = (unsigned int)__bfloat16_as_ushort(xl) |
         ((unsigned int)__bfloat16_as_ushort(yl) << 16);
}

// ---------------------------------------------------------------------------
// Elementwise fp32 -> (hi, lo) bf16 split
// ---------------------------------------------------------------------------
__global__ void split_fp32(const float* __restrict__ in,
                           __nv_bfloat16* __restrict__ H,
                           __nv_bfloat16* __restrict__ L, int n4) {
    int i = blockIdx.x * blockDim.x + threadIdx.x;
    if (i >= n4) return;
    float4 v = reinterpret_cast<const float4*>(in)[i];
    float f[4] = {v.x, v.y, v.z, v.w};
    Pack4 Hp, Lp;
    #pragma unroll
    for (int j = 0; j < 4; j++) {
        __nv_bfloat16 hv = __float2bfloat16_rn(f[j]);
        Hp.h[j] = hv;
        Lp.h[j] = __float2bfloat16_rn(f[j] - __bfloat162float(hv));
    }
    reinterpret_cast<uint2*>(H)[i] = Hp.u;
    reinterpret_cast<uint2*>(L)[i] = Lp.u;
}

// ---------------------------------------------------------------------------
// RMSNorm with split epilogue: one block per row, writes bf16 hi/lo
// ---------------------------------------------------------------------------
__global__ void rmsnorm_split_kernel(const float* __restrict__ x,
                                     __nv_bfloat16* __restrict__ H,
                                     __nv_bfloat16* __restrict__ L) {
    int row = blockIdx.x;
    const float* xr = x + (size_t)row * CC;
    float ss = 0.f;
    for (int c = threadIdx.x; c < CC; c += blockDim.x) {
        float vv = xr[c];
        ss += vv * vv;
    }
    __shared__ float red[32];
    #pragma unroll
    for (int off = 16; off; off >>= 1) ss += __shfl_xor_sync(0xffffffffu, ss, off);
    int wid = threadIdx.x >> 5, lane = threadIdx.x & 31;
    if (lane == 0) red[wid] = ss;
    __syncthreads();
    if (wid == 0) {
        float v2 = lane < (blockDim.x >> 5) ? red[lane] : 0.f;
        #pragma unroll
        for (int off = 16; off; off >>= 1) v2 += __shfl_xor_sync(0xffffffffu, v2, off);
        if (lane == 0) red[0] = rsqrtf(v2 / (float)CC + EPS);
    }
    __syncthreads();
    float r = red[0];
    size_t base = (size_t)row * CC;
    for (int c = threadIdx.x * 2; c < CC; c += blockDim.x * 2) {
        float a = xr[c] * r, b = xr[c + 1] * r;
        unsigned int hi, lo;
        split_pack2(a, b, hi, lo);
        *reinterpret_cast<unsigned int*>(&H[base + c]) = hi;
        *reinterpret_cast<unsigned int*>(&L[base + c]) = lo;
    }
}

// ---------------------------------------------------------------------------
// bf16x3 GEMM, pre-split operands, cp.async 3-stage pipeline.
// C[M,N] = (AH+AL)[M,K] @ (BH+BL)[N,K]^T (3-term split product)
// Block 128x128x32, 512 threads, warp 32x32; fragment layout = proven R5.
// ---------------------------------------------------------------------------
enum { EPI_F32 = 0, EPI_ADDF = 1, EPI_RELU2S = 2 };

#define GP_PART   10240              // bytes per part (128 rows x 80B pitch)
#define GP_STAGE  (4*GP_PART)        // AH,AL,BH,BL
#define GP_NSTG   3
#define GP_SMEM   (GP_NSTG*GP_STAGE) // 122880 bytes

__device__ __forceinline__ void gp_issue(
    uint32_t sb32, int buf, int tid,
    const __nv_bfloat16* __restrict__ AH, const __nv_bfloat16* __restrict__ AL,
    const __nv_bfloat16* __restrict__ BH, const __nv_bfloat16* __restrict__ BL,
    int bm, int bn, int K, int k0)
{
    int row = tid >> 2, c = tid & 3;
    size_t offA = (size_t)(bm + row) * K + k0 + c * 8;
    size_t offB = (size_t)(bn + row) * K + k0 + c * 8;
    uint32_t d = sb32 + buf * GP_STAGE + row * 80 + c * 16;
    cpasync16(d,               AH + offA);
    cpasync16(d + GP_PART,     AL + offA);
    cpasync16(d + 2 * GP_PART, BH + offB);
    cpasync16(d + 3 * GP_PART, BL + offB);
}

template <int EPI>
__global__ __launch_bounds__(512, 1) void gemm_pre(
    const __nv_bfloat16* __restrict__ AH, const __nv_bfloat16* __restrict__ AL,
    const __nv_bfloat16* __restrict__ BH, const __nv_bfloat16* __restrict__ BL,
    const float* __restrict__ Res, float* __restrict__ C,
    __nv_bfloat16* __restrict__ CH, __nv_bfloat16* __restrict__ CL,
    int M, int N, int K)
{
    extern __shared__ char smp[];
    uint32_t sb32 = smem_u32(smp);
    int tid = threadIdx.x;
    int bm = blockIdx.y * 128;
    int bn = blockIdx.x * 128;
    int wid = tid >> 5, lane = tid & 31;
    int wm = (wid & 3) * 32;
    int wn = (wid >> 2) * 32;
    int lt = lane >> 2, g = lane & 3;

    float acc[2][4][4];
    #pragma unroll
    for (int i = 0; i < 2; i++)
        #pragma unroll
        for (int j = 0; j < 4; j++)
            #pragma unroll
            for (int r = 0; r < 4; r++) acc[i][j][r] = 0.f;

    int nst = K / 32;
    #pragma unroll
    for (int p = 0; p < 2; p++) {
        gp_issue(sb32, p, tid, AH, AL, BH, BL, bm, bn, K, p * 32);
        CP_COMMIT();
    }

    for (int it = 0; it < nst; it++) {
        if (it + 1 < nst) { CP_WAIT(1); } else { CP_WAIT(0); }
        __syncthreads();

        int b = it - (it / 3) * 3;   // it % 3
        const unsigned int* base =
            reinterpret_cast<const unsigned int*>(smp + b * GP_STAGE);
        const unsigned int* AHw = base;
        const unsigned int* ALw = base + 2560;
        const unsigned int* BHw = base + 5120;
        const unsigned int* BLw = base + 7680;

        #pragma unroll
        for (int kk2 = 0; kk2 < 2; kk2++) {
            int kw = kk2 * 8;
            unsigned int ah[2][4], al[2][4];
            #pragma unroll
            for (int mi = 0; mi < 2; mi++) {
                int m0 = wm + mi * 16 + lt;
                int base0 = m0 * 20 + kw + g;
                int base1 = (m0 + 8) * 20 + kw + g;
                ah[mi][0] = AHw[base0];
                ah[mi][1] = AHw[base1];
                ah[mi][2] = AHw[base0 + 4];
                ah[mi][3] = AHw[base1 + 4];
                al[mi][0] = ALw[base0];
                al[mi][1] = ALw[base1];
                al[mi][2] = ALw[base0 + 4];
                al[mi][3] = ALw[base1 + 4];
            }
            #pragma unroll
            for (int ni = 0; ni < 4; ni++) {
                int n0 = wn + ni * 8 + lt;
                int nb = n0 * 20 + kw + g;
                unsigned int bh0 = BHw[nb], bh1 = BHw[nb + 4];
                unsigned int bl0 = BLw[nb], bl1 = BLw[nb + 4];
                #pragma unroll
                for (int mi = 0; mi < 2; mi++) {
                    MMA_BF16(acc[mi][ni], ah[mi], bh0, bh1);
                    MMA_BF16(acc[mi][ni], ah[mi], bl0, bl1);
                    MMA_BF16(acc[mi][ni], al[mi], bh0, bh1);
                }
            }
        }

        if (it + 2 < nst) {
            int nb3 = (it + 2) - ((it + 2) / 3) * 3;
            gp_issue(sb32, nb3, tid, AH, AL, BH, BL, bm, bn, K, (it + 2) * 32);
            CP_COMMIT();
        }
    }

    // epilogue
    #pragma unroll
    for (int mi = 0; mi < 2; mi++) {
        #pragma unroll
        for (int ni = 0; ni < 4; ni++) {
            int r0 = bm + wm + mi * 16 + lt;
            int c0 = bn + wn + ni * 8 + g * 2;
            float2 v0 = {acc[mi][ni][0], acc[mi][ni][1]};
            float2 v1 = {acc[mi][ni][2], acc[mi][ni][3]};
            if (EPI == EPI_RELU2S) {
                v0.x = fmaxf(v0.x, 0.f); v0.x *= v0.x;
                v0.y = fmaxf(v0.y, 0.f); v0.y *= v0.y;
                v1.x = fmaxf(v1.x, 0.f); v1.x *= v1.x;
                v1.y = fmaxf(v1.y, 0.f); v1.y *= v1.y;
                unsigned int h0, l0, h1, l1;
                split_pack2(v0.x, v0.y, h0, l0);
                split_pack2(v1.x, v1.y, h1, l1);
                *reinterpret_cast<unsigned int*>(&CH[(size_t)r0 * N + c0]) = h0;
                *reinterpret_cast<unsigned int*>(&CL[(size_t)r0 * N + c0]) = l0;
                *reinterpret_cast<unsigned int*>(&CH[(size_t)(r0 + 8) * N + c0]) = h1;
                *reinterpret_cast<unsigned int*>(&CL[(size_t)(r0 + 8) * N + c0]) = l1;
            } else {
                if (EPI == EPI_ADDF) {
                    float2 r0v = *reinterpret_cast<const float2*>(&Res[(size_t)r0 * N + c0]);
                    float2 r1v = *reinterpret_cast<const float2*>(&Res[(size_t)(r0 + 8) * N + c0]);
                    v0.x += r0v.x; v0.y += r0v.y;
                    v1.x += r1v.x; v1.y += r1v.y;
                }
                *reinterpret_cast<float2*>(&C[(size_t)r0 * N + c0]) = v0;
                *reinterpret_cast<float2*>(&C[(size_t)(r0 + 8) * N + c0]) = v1;
            }
        }
    }
}

// ---------------------------------------------------------------------------
// bf16x3 flash attention via mma.sync (R9, epilogue writes split bf16)
// ---------------------------------------------------------------------------
#define AQH 0
#define AQL 8704
#define AKH 17408
#define AKL 26112
#define AVH 34816
#define AVL 44032
#define ATT_SMEM 106496   // bytes
#define WQH 0
#define WQL 4352
#define WKH 8704
#define WKL 13056
#define WVH 17408
#define WVL 22016

__global__ __launch_bounds__(128) void attn_mma(
    const float* __restrict__ q, const float* __restrict__ k,
    const float* __restrict__ v,
    __nv_bfloat16* __restrict__ oH, __nv_bfloat16* __restrict__ oL)
{
    extern __shared__ char attsm[];
    __nv_bfloat16* sb = reinterpret_cast<__nv_bfloat16*>(attsm);
    unsigned int* s32 = reinterpret_cast<unsigned int*>(attsm);

    int tid = threadIdx.x;
    int wid = tid >> 5, lane = tid & 31;
    int lt = lane >> 2, g = lane & 3;
    int wrow = wid * 16;
    int qt = blockIdx.x, h = blockIdx.y, b = blockIdx.z;
    int qb = qt * 64;
    const float scale = 0.08838834764831845f;  // 1/sqrt(128)
    size_t base = ((size_t)b * TT) * CC + (size_t)h * HD;

    #pragma unroll
    for (int i = 0; i < 16; i++) {
        int lin = tid + i * 128;
        int r = lin >> 5, c4 = (lin & 31) * 4;
        float4 vq = *reinterpret_cast<const float4*>(&q[base + (size_t)(qb + r) * CC + c4]);
        float f[4] = {vq.x * scale, vq.y * scale, vq.z * scale, vq.w * scale};
        Pack4 H, L;
        #pragma unroll
        for (int j = 0; j < 4; j++) {
            __nv_bfloat16 hv = __float2bfloat16_rn(f[j]);
            H.h[j] = hv;
            L.h[j] = __float2bfloat16_rn(f[j] - __bfloat162float(hv));
        }
        *reinterpret_cast<uint2*>(&sb[AQH + r * 136 + c4]) = H.u;
        *reinterpret_cast<uint2*>(&sb[AQL + r * 136 + c4]) = L.u;
    }

    float oacc[16][4];
    #pragma unroll
    for (int i = 0; i < 16; i++)
        #pragma unroll
        for (int j = 0; j < 4; j++) oacc[i][j] = 0.f;
    float m0 = -1e30f, m1 = -1e30f, l0 = 0.f, l1 = 0.f;

    for (int nt = 0; nt <= qt; nt++) {
        int kb = nt * 64;
        #pragma unroll
        for (int i = 0; i < 16; i++) {
            int lin = tid + i * 128;
            int r = lin >> 5, c4 = (lin & 31) * 4;
            float4 vk = *reinterpret_cast<const float4*>(&k[base + (size_t)(kb + r) * CC + c4]);
            float f[4] = {vk.x, vk.y, vk.z, vk.w};
            Pack4 H, L;
            #pragma unroll
            for (int j = 0; j < 4; j++) {
                __nv_bfloat16 hv = __float2bfloat16_rn(f[j]);
                H.h[j] = hv;
                L.h[j] = __float2bfloat16_rn(f[j] - __bfloat162float(hv));
            }
            *reinterpret_cast<uint2*>(&sb[AKH + r * 136 + c4]) = H.u;
            *reinterpret_cast<uint2*>(&sb[AKL + r * 136 + c4]) = L.u;
        }
        #pragma unroll
        for (int i = 0; i < 16; i++) {
            int lin = tid + i * 128;
            int r = lin & 63;
            int c4 = ((lin >> 6) & 31) * 4;
            float4 vv = *reinterpret_cast<const float4*>(&v[base + (size_t)(kb + r) * CC + c4]);
            float f[4] = {vv.x, vv.y, vv.z, vv.w};
            #pragma unroll
            for (int j = 0; j < 4; j++) {
                __nv_bfloat16 hv = __float2bfloat16_rn(f[j]);
                sb[AVH + (c4 + j) * 72 + r] = hv;
                sb[AVL + (c4 + j) * 72 + r] = __float2bfloat16_rn(f[j] - __bfloat162float(hv));
            }
        }
        __syncthreads();

        float sacc[8][4];
        #pragma unroll
        for (int i = 0; i < 8; i++)
            #pragma unroll
            for (int j = 0; j < 4; j++) sacc[i][j] = 0.f;

        #pragma unroll
        for (int ks = 0; ks < 8; ks++) {
            unsigned int aH[4], aL[4];
            int ab = (wrow + lt) * 68 + ks * 8 + g;
            aH[0] = s32[WQH + ab];       aH[1] = s32[WQH + ab + 544];
            aH[2] = s32[WQH + ab + 4];   aH[3] = s32[WQH + ab + 548];
            aL[0] = s32[WQL + ab];       aL[1] = s32[WQL + ab + 544];
            aL[2] = s32[WQL + ab + 4];   aL[3] = s32[WQL + ab + 548];
            #pragma unroll
            for (int ni = 0; ni < 8; ni++) {
                int bb = (ni * 8 + lt) * 68 + ks * 8 + g;
                unsigned int bh0 = s32[WKH + bb], bh1 = s32[WKH + bb + 4];
                unsigned int bl0 = s32[WKL + bb], bl1 = s32[WKL + bb + 4];
                MMA_BF16(sacc[ni], aH, bh0, bh1);
                MMA_BF16(sacc[ni], aH, bl0, bl1);
                MMA_BF16(sacc[ni], aL, bh0, bh1);
            }
        }

        if (nt == qt) {
            int row0 = qb + wrow + lt, row1 = row0 + 8;
            #pragma unroll
            for (int ni = 0; ni < 8; ni++) {
                int c0 = kb + ni * 8 + 2 * g;
                if (c0 > row0)     sacc[ni][0] = -1e30f;
                if (c0 + 1 > row0) sacc[ni][1] = -1e30f;
                if (c0 > row1)     sacc[ni][2] = -1e30f;
                if (c0 + 1 > row1) sacc[ni][3] = -1e30f;
            }
        }

        float rm0 = -1e30f, rm1 = -1e30f;
        #pragma unroll
        for (int ni = 0; ni < 8; ni++) {
            rm0 = fmaxf(rm0, fmaxf(sacc[ni][0], sacc[ni][1]));
            rm1 = fmaxf(rm1, fmaxf(sacc[ni][2], sacc[ni][3]));
        }
        rm0 = fmaxf(rm0, __shfl_xor_sync(0xffffffffu, rm0, 1));
        rm0 = fmaxf(rm0, __shfl_xor_sync(0xffffffffu, rm0, 2));
        rm1 = fmaxf(rm1, __shfl_xor_sync(0xffffffffu, rm1, 1));
        rm1 = fmaxf(rm1, __shfl_xor_sync(0xffffffffu, rm1, 2));
        float mn0 = fmaxf(m0, rm0), mn1 = fmaxf(m1, rm1);
        float al0 = __expf(m0 - mn0), al1 = __expf(m1 - mn1);
        m0 = mn0; m1 = mn1;
        float rs0 = 0.f, rs1 = 0.f;
        #pragma unroll
        for (int ni = 0; ni < 8; ni++) {
            sacc[ni][0] = __expf(sacc[ni][0] - m0);
            sacc[ni][1] = __expf(sacc[ni][1] - m0);
            sacc[ni][2] = __expf(sacc[ni][2] - m1);
            sacc[ni][3] = __expf(sacc[ni][3] - m1);
            rs0 += sacc[ni][0] + sacc[ni][1];
            rs1 += sacc[ni][2] + sacc[ni][3];
        }
        l0 = l0 * al0 + rs0;
        l1 = l1 * al1 + rs1;
        #pragma unroll
        for (int ni = 0; ni < 16; ni++) {
            oacc[ni][0] *= al0; oacc[ni][1] *= al0;
            oacc[ni][2] *= al1; oacc[ni][3] *= al1;
        }

        #pragma unroll
        for (int kk = 0; kk < 4; kk++) {
            unsigned int pH[4], pL[4];
            split_pack2(sacc[2 * kk][0],     sacc[2 * kk][1],     pH[0], pL[0]);
            split_pack2(sacc[2 * kk][2],     sacc[2 * kk][3],     pH[1], pL[1]);
            split_pack2(sacc[2 * kk + 1][0], sacc[2 * kk + 1][1], pH[2], pL[2]);
            split_pack2(sacc[2 * kk + 1][2], sacc[2 * kk + 1][3], pH[3], pL[3]);
            #pragma unroll
            for (int ni = 0; ni < 16; ni++) {
                int vb2 = (ni * 8 + lt) * 36 + kk * 8 + g;
                unsigned int vh0 = s32[WVH + vb2], vh1 = s32[WVH + vb2 + 4];
                unsigned int vl0 = s32[WVL + vb2], vl1 = s32[WVL + vb2 + 4];
                MMA_BF16(oacc[ni], pH, vh0, vh1);
                MMA_BF16(oacc[ni], pH, vl0, vl1);
                MMA_BF16(oacc[ni], pL, vh0, vh1);
            }
        }
        __syncthreads();
    }

    l0 += __shfl_xor_sync(0xffffffffu, l0, 1);
    l0 += __shfl_xor_sync(0xffffffffu, l0, 2);
    l1 += __shfl_xor_sync(0xffffffffu, l1, 1);
    l1 += __shfl_xor_sync(0xffffffffu, l1, 2);
    float inv0 = 1.f / l0, inv1 = 1.f / l1;
    int row0 = qb + wrow + lt;
    #pragma unroll
    for (int ni = 0; ni < 16; ni++) {
        size_t o0 = base + (size_t)row0 * CC + ni * 8 + 2 * g;
        size_t o1 = o0 + (size_t)8 * CC;
        unsigned int h0, l0u, h1, l1u;
        split_pack2(oacc[ni][0] * inv0, oacc[ni][1] * inv0, h0, l0u);
        split_pack2(oacc[ni][2] * inv1, oacc[ni][3] * inv1, h1, l1u);
        *reinterpret_cast<unsigned int*>(&oH[o0]) = h0;
        *reinterpret_cast<unsigned int*>(&oL[o0]) = l0u;
        *reinterpret_cast<unsigned int*>(&oH[o1]) = h1;
        *reinterpret_cast<unsigned int*>(&oL[o1]) = l1u;
    }
}

// ---------------------------------------------------------------------------
// Launch
// ---------------------------------------------------------------------------
extern "C" void kernel_launch(void* const* d_in, const int* in_sizes, int n_in,
                              void* d_out, int out_size) {
    const float* x   = (const float*)d_in[0];
    const float* wq  = (const float*)d_in[1];
    const float* wk  = (const float*)d_in[2];
    const float* wv  = (const float*)d_in[3];
    const float* wo  = (const float*)d_in[4];
    const float* fc1 = (const float*)d_in[5];
    const float* fc2 = (const float*)d_in[6];
    float* out = (float*)d_out;

    float *q, *k, *v, *x1;
    cudaGetSymbolAddress((void**)&q,  g_q);
    cudaGetSymbolAddress((void**)&k,  g_k);
    cudaGetSymbolAddress((void**)&v,  g_v);
    cudaGetSymbolAddress((void**)&x1, g_x1);

    __nv_bfloat16 *hH, *hL, *attH, *attL, *mH, *mL;
    __nv_bfloat16 *wqH, *wqL, *wkH, *wkL, *wvH, *wvL, *woH, *woL;
    __nv_bfloat16 *fc1H, *fc1L, *fc2H, *fc2L;
    cudaGetSymbolAddress((void**)&hH, g_hH);     cudaGetSymbolAddress((void**)&hL, g_hL);
    cudaGetSymbolAddress((void**)&attH, g_attH); cudaGetSymbolAddress((void**)&attL, g_attL);
    cudaGetSymbolAddress((void**)&mH, g_mH);     cudaGetSymbolAddress((void**)&mL, g_mL);
    cudaGetSymbolAddress((void**)&wqH, g_wqH);   cudaGetSymbolAddress((void**)&wqL, g_wqL);
    cudaGetSymbolAddress((void**)&wkH, g_wkH);   cudaGetSymbolAddress((void**)&wkL, g_wkL);
    cudaGetSymbolAddress((void**)&wvH, g_wvH);   cudaGetSymbolAddress((void**)&wvL, g_wvL);
    cudaGetSymbolAddress((void**)&woH, g_woH);   cudaGetSymbolAddress((void**)&woL, g_woL);
    cudaGetSymbolAddress((void**)&fc1H, g_fc1H); cudaGetSymbolAddress((void**)&fc1L, g_fc1L);
    cudaGetSymbolAddress((void**)&fc2H, g_fc2H); cudaGetSymbolAddress((void**)&fc2L, g_fc2L);

    cudaFuncSetAttribute(attn_mma, cudaFuncAttributeMaxDynamicSharedMemorySize, ATT_SMEM);
    cudaFuncSetAttribute(gemm_pre<EPI_F32>,    cudaFuncAttributeMaxDynamicSharedMemorySize, GP_SMEM);
    cudaFuncSetAttribute(gemm_pre<EPI_ADDF>,   cudaFuncAttributeMaxDynamicSharedMemorySize, GP_SMEM);
    cudaFuncSetAttribute(gemm_pre<EPI_RELU2S>, cudaFuncAttributeMaxDynamicSharedMemorySize, GP_SMEM);

    // 0) split weights (deterministic, every call)
    {
        int n4w = CC * CC / 4;
        int n4f = MLPD * CC / 4;
        split_fp32<<<(n4w + 255) / 256, 256>>>(wq, wqH, wqL, n4w);
        split_fp32<<<(n4w + 255) / 256, 256>>>(wk, wkH, wkL, n4w);
        split_fp32<<<(n4w + 255) / 256, 256>>>(wv, wvH, wvL, n4w);
        split_fp32<<<(n4w + 255) / 256, 256>>>(wo, woH, woL, n4w);
        split_fp32<<<(n4f + 255) / 256, 256>>>(fc1, fc1H, fc1L, n4f);
        split_fp32<<<(n4f + 255) / 256, 256>>>(fc2, fc2H, fc2L, n4f);
    }

    // 1) h = rmsnorm(x)  (split)
    rmsnorm_split_kernel<<<BT, 256>>>(x, hH, hL);

    // 2-4) q,k,v = h @ w^T  (fp32 out for attention)
    dim3 thr(512);
    dim3 g_qkv(CC / 128, BT / 128);
    gemm_pre<EPI_F32><<<g_qkv, thr, GP_SMEM>>>(hH, hL, wqH, wqL, nullptr, q, nullptr, nullptr, BT, CC, CC);
    gemm_pre<EPI_F32><<<g_qkv, thr, GP_SMEM>>>(hH, hL, wkH, wkL, nullptr, k, nullptr, nullptr, BT, CC, CC);
    gemm_pre<EPI_F32><<<g_qkv, thr, GP_SMEM>>>(hH, hL, wvH, wvL, nullptr, v, nullptr, nullptr, BT, CC, CC);

    // 5) causal attention -> split att
    dim3 g_att_grid(TT / 64, HH, BB);
    attn_mma<<<g_att_grid, 128, ATT_SMEM>>>(q, k, v, attH, attL);

    // 6) x1 = x + att @ wo^T
    gemm_pre<EPI_ADDF><<<g_qkv, thr, GP_SMEM>>>(attH, attL, woH, woL, x, x1, nullptr, nullptr, BT, CC, CC);

    // 7) h = rmsnorm(x1)  (split)
    rmsnorm_split_kernel<<<BT, 256>>>(x1, hH, hL);

    // 8) m = relu(h @ fc1^T)^2  (split out)
    dim3 g_fc1(MLPD / 128, BT / 128);
    gemm_pre<EPI_RELU2S><<<g_fc1, thr, GP_SMEM>>>(hH, hL, fc1H, fc1L, nullptr, nullptr, mH, mL, BT, MLPD, CC);

    // 9) out = x1 + m @ fc2^T
    dim3 g_fc2(CC / 128, BT / 128);
    gemm_pre<EPI_ADDF><<<g_fc2, thr, GP_SMEM>>>(mH, mL, fc2H, fc2L, x1, out, BT == 0 ? nullptr : nullptr, nullptr, BT, CC, MLPD);
}